// round 2
// baseline (speedup 1.0000x reference)
#include <cuda_runtime.h>
#include <cuda_bf16.h>

#define N_NODES 50000
#define D_IN    128
#define D_HID   256
#define E_MAX   800000

// Scratch (allocation-free rule: __device__ globals)
__device__ float g_agg[N_NODES * D_HID];
__device__ float g_t1 [N_NODES * D_HID];
__device__ float g_h0 [N_NODES * D_HID];
__device__ int   g_ei32[2 * E_MAX];
__device__ int   g_mode;   // 1 = input is int64, 0 = input is int32

// ---------------------------------------------------------------------------
// Detect edge-index dtype. If the buffer really holds int64 indices, every
// int64-interpreted value is in [0, N). If it holds int32, the int64 view
// fuses two random indices -> hi word nonzero -> value >= N almost surely.
// ---------------------------------------------------------------------------
__global__ void detect_kernel(const void* __restrict__ ei_raw, int nscan) {
    if (threadIdx.x == 0 && blockIdx.x == 0) {
        const long long* p = (const long long*)ei_raw;
        int is64 = 1;
        for (int i = 0; i < nscan; i++) {
            long long v = p[i];
            if (v < 0 || v >= N_NODES) { is64 = 0; break; }
        }
        g_mode = is64;
    }
}

__global__ void convert_kernel(const void* __restrict__ ei_raw,
                               int* __restrict__ out, int n) {
    int i = blockIdx.x * blockDim.x + threadIdx.x;
    if (i >= n) return;
    if (g_mode) {
        out[i] = (int)((const long long*)ei_raw)[i];
    } else {
        out[i] = ((const int*)ei_raw)[i];
    }
}

// ---------------------------------------------------------------------------
// Zero-fill (agg must start at 0 before scatter-add)
// ---------------------------------------------------------------------------
__global__ void zero_kernel(float4* __restrict__ p, int n4) {
    int i = blockIdx.x * blockDim.x + threadIdx.x;
    if (i < n4) p[i] = make_float4(0.f, 0.f, 0.f, 0.f);
}

// ---------------------------------------------------------------------------
// Scatter-add: agg[dst] += x[src], row width D = 4 << shift floats.
// One thread handles one float4 of one edge row; consecutive threads cover
// consecutive chunks of the same row (coalesced gather + coalesced red.v4).
// ---------------------------------------------------------------------------
__global__ void scatter_kernel(const float4* __restrict__ x,
                               const int* __restrict__ ei,  // [2, E] int32
                               float* __restrict__ agg,
                               int E, int shift) {
    int idx = blockIdx.x * blockDim.x + threadIdx.x;
    int total = E << shift;
    if (idx >= total) return;
    int e = idx >> shift;
    int c = idx & ((1 << shift) - 1);
    int D4 = 1 << shift;
    int s = ei[e];
    int d = ei[E + e];
    float4 v = __ldg(x + (long long)s * D4 + c);
    float* p = agg + (((long long)d * D4 + c) << 2);
    asm volatile("red.global.add.v4.f32 [%0], {%1,%2,%3,%4};"
                 :: "l"(p), "f"(v.x), "f"(v.y), "f"(v.z), "f"(v.w)
                 : "memory");
}

// ---------------------------------------------------------------------------
// Tiled SGEMM:  C[M,Ncol] = op(Aeff @ W + bias)
//   Aeff = COMBINE ? (1+eps)*A + A2 : A      (GIN combine folded into A load)
//   op   = RELU ? relu : identity
// BM=BN=64, BK=16, 256 threads, 4x4 microtile per thread.
// ---------------------------------------------------------------------------
template<bool COMBINE, bool RELU>
__global__ __launch_bounds__(256)
void gemm_kernel(const float* __restrict__ A,
                 const float* __restrict__ A2,
                 const float* __restrict__ epsp,
                 const float* __restrict__ W,
                 const float* __restrict__ bias,
                 float* __restrict__ C,
                 int M, int K, int Ncol) {
    constexpr int BM = 64, BN = 64, BK = 16;
    __shared__ __align__(16) float As[BK][BM];   // transposed A tile
    __shared__ __align__(16) float Bs[BK][BN];

    const int tid  = threadIdx.x;
    const int row0 = blockIdx.x * BM;
    const int col0 = blockIdx.y * BN;

    float scale = 1.0f;
    if (COMBINE) scale = 1.0f + __ldg(epsp);

    // A-tile load: 256 threads x float4 covers 64x16
    const int la_r = tid >> 2;          // 0..63
    const int la_k = (tid & 3) * 4;     // 0,4,8,12
    // B-tile load: 256 threads x float4 covers 16x64
    const int lb_k = tid >> 4;          // 0..15
    const int lb_c = (tid & 15) * 4;    // 0..60
    // compute microtile
    const int tm = (tid >> 4) * 4;      // 0..60
    const int tn = (tid & 15) * 4;      // 0..60

    float acc[4][4] = {};

    for (int k0 = 0; k0 < K; k0 += BK) {
        // ---- load A tile (with fused GIN combine) ----
        int ar = row0 + la_r;
        float4 av = make_float4(0.f, 0.f, 0.f, 0.f);
        if (ar < M) {
            av = *reinterpret_cast<const float4*>(A + (long long)ar * K + k0 + la_k);
            if (COMBINE) {
                float4 gv = *reinterpret_cast<const float4*>(A2 + (long long)ar * K + k0 + la_k);
                av.x = fmaf(scale, av.x, gv.x);
                av.y = fmaf(scale, av.y, gv.y);
                av.z = fmaf(scale, av.z, gv.z);
                av.w = fmaf(scale, av.w, gv.w);
            }
        }
        As[la_k + 0][la_r] = av.x;
        As[la_k + 1][la_r] = av.y;
        As[la_k + 2][la_r] = av.z;
        As[la_k + 3][la_r] = av.w;

        // ---- load B tile ----
        float4 wv = *reinterpret_cast<const float4*>(
            W + (long long)(k0 + lb_k) * Ncol + col0 + lb_c);
        *reinterpret_cast<float4*>(&Bs[lb_k][lb_c]) = wv;

        __syncthreads();

        // ---- compute ----
        #pragma unroll
        for (int kk = 0; kk < BK; kk++) {
            float4 a4 = *reinterpret_cast<const float4*>(&As[kk][tm]);
            float4 b4 = *reinterpret_cast<const float4*>(&Bs[kk][tn]);
            float avv[4] = {a4.x, a4.y, a4.z, a4.w};
            float bvv[4] = {b4.x, b4.y, b4.z, b4.w};
            #pragma unroll
            for (int i = 0; i < 4; i++)
                #pragma unroll
                for (int j = 0; j < 4; j++)
                    acc[i][j] = fmaf(avv[i], bvv[j], acc[i][j]);
        }
        __syncthreads();
    }

    // ---- epilogue ----
    float4 bb = *reinterpret_cast<const float4*>(bias + col0 + tn);
    float bv[4] = {bb.x, bb.y, bb.z, bb.w};
    #pragma unroll
    for (int i = 0; i < 4; i++) {
        int r = row0 + tm + i;
        if (r < M) {
            float4 o;
            float v0 = acc[i][0] + bv[0];
            float v1 = acc[i][1] + bv[1];
            float v2 = acc[i][2] + bv[2];
            float v3 = acc[i][3] + bv[3];
            if (RELU) {
                v0 = fmaxf(v0, 0.f); v1 = fmaxf(v1, 0.f);
                v2 = fmaxf(v2, 0.f); v3 = fmaxf(v3, 0.f);
            }
            o.x = v0; o.y = v1; o.z = v2; o.w = v3;
            *reinterpret_cast<float4*>(C + (long long)r * Ncol + col0 + tn) = o;
        }
    }
}

// ---------------------------------------------------------------------------
// Launch: edge-index normalize + two GIN layers + output FC
// ---------------------------------------------------------------------------
extern "C" void kernel_launch(void* const* d_in, const int* in_sizes, int n_in,
                              void* d_out, int out_size) {
    const float* x    = (const float*)d_in[0];
    const void*  eiRaw= d_in[1];
    const float* eps0 = (const float*)d_in[2];
    const float* W1_0 = (const float*)d_in[3];
    const float* b1_0 = (const float*)d_in[4];
    const float* W2_0 = (const float*)d_in[5];
    const float* b2_0 = (const float*)d_in[6];
    const float* eps1 = (const float*)d_in[7];
    const float* W1_1 = (const float*)d_in[8];
    const float* b1_1 = (const float*)d_in[9];
    const float* W2_1 = (const float*)d_in[10];
    const float* b2_1 = (const float*)d_in[11];
    const float* Wo   = (const float*)d_in[12];
    const float* bo   = (const float*)d_in[13];
    float*       out  = (float*)d_out;

    const int two_e = in_sizes[1];
    const int E     = two_e / 2;

    float *agg, *t1, *h0;
    int   *ei;
    cudaGetSymbolAddress((void**)&agg, g_agg);
    cudaGetSymbolAddress((void**)&t1,  g_t1);
    cudaGetSymbolAddress((void**)&h0,  g_h0);
    cudaGetSymbolAddress((void**)&ei,  g_ei32);

    // ---- normalize edge index to int32 ----
    int nscan = two_e < 128 ? two_e : 128;
    detect_kernel<<<1, 32>>>(eiRaw, nscan);
    convert_kernel<<<(two_e + 255) / 256, 256>>>(eiRaw, ei, two_e);

    dim3 blk(256);
    dim3 gH((N_NODES + 63) / 64, D_HID / 64);   // Ncol=256
    dim3 gO((N_NODES + 63) / 64, D_IN  / 64);   // Ncol=128

    // ---- layer 0 (D_IN -> D_HID) ----
    {
        int n4 = N_NODES * D_IN / 4;
        zero_kernel<<<(n4 + 255) / 256, 256>>>((float4*)agg, n4);
        long long tot = (long long)E << 5;  // E * 32 float4-chunks
        scatter_kernel<<<(int)((tot + 255) / 256), 256>>>((const float4*)x, ei, agg, E, 5);
    }
    gemm_kernel<true, true ><<<gH, blk>>>(x,  agg,  eps0, W1_0, b1_0, t1, N_NODES, D_IN,  D_HID);
    gemm_kernel<false,false><<<gH, blk>>>(t1, nullptr, nullptr, W2_0, b2_0, h0, N_NODES, D_HID, D_HID);

    // ---- layer 1 (D_HID -> D_HID) ----
    {
        int n4 = N_NODES * D_HID / 4;
        zero_kernel<<<(n4 + 255) / 256, 256>>>((float4*)agg, n4);
        long long tot = (long long)E << 6;  // E * 64 float4-chunks
        scatter_kernel<<<(int)((tot + 255) / 256), 256>>>((const float4*)h0, ei, agg, E, 6);
    }
    gemm_kernel<true, true ><<<gH, blk>>>(h0, agg,  eps1, W1_1, b1_1, t1, N_NODES, D_HID, D_HID);
    // reuse agg buffer as h1 (agg no longer needed after this point)
    gemm_kernel<false,false><<<gH, blk>>>(t1, nullptr, nullptr, W2_1, b2_1, agg, N_NODES, D_HID, D_HID);

    // ---- fc_out (D_HID -> D_IN) ----
    gemm_kernel<false,false><<<gO, blk>>>(agg, nullptr, nullptr, Wo, bo, out, N_NODES, D_HID, D_IN);
}

// round 3
// speedup vs baseline: 2.4474x; 2.4474x over previous
#include <cuda_runtime.h>
#include <cuda_bf16.h>
#include <cstdint>
#include <cstddef>

#define N_NODES 50000
#define D_IN    128
#define D_HID   256
#define E_MAX   800000

// Scratch (allocation-free rule: __device__ globals)
__device__ float g_agg[N_NODES * D_HID];
__device__ float g_t1 [N_NODES * D_HID];
__device__ float g_h0 [N_NODES * D_HID];
__device__ int   g_ei32[2 * E_MAX];
__device__ int   g_mode;   // 1 = input is int64, 0 = input is int32

// ---------------------------------------------------------------------------
// Edge-index dtype detect + convert (harness may deliver int64 as int32)
// ---------------------------------------------------------------------------
__global__ void detect_kernel(const void* __restrict__ ei_raw, int nscan) {
    if (threadIdx.x == 0 && blockIdx.x == 0) {
        const long long* p = (const long long*)ei_raw;
        int is64 = 1;
        for (int i = 0; i < nscan; i++) {
            long long v = p[i];
            if (v < 0 || v >= N_NODES) { is64 = 0; break; }
        }
        g_mode = is64;
    }
}

__global__ void convert_kernel(const void* __restrict__ ei_raw,
                               int* __restrict__ out, int n) {
    int i = blockIdx.x * blockDim.x + threadIdx.x;
    if (i >= n) return;
    if (g_mode) {
        out[i] = (int)((const long long*)ei_raw)[i];
    } else {
        out[i] = ((const int*)ei_raw)[i];
    }
}

// ---------------------------------------------------------------------------
// Zero-fill
// ---------------------------------------------------------------------------
__global__ void zero_kernel(float4* __restrict__ p, int n4) {
    int i = blockIdx.x * blockDim.x + threadIdx.x;
    if (i < n4) p[i] = make_float4(0.f, 0.f, 0.f, 0.f);
}

// ---------------------------------------------------------------------------
// Scatter-add: agg[dst] += x[src], row width D = 4 << shift floats.
// ---------------------------------------------------------------------------
__global__ void scatter_kernel(const float4* __restrict__ x,
                               const int* __restrict__ ei,  // [2, E] int32
                               float* __restrict__ agg,
                               int E, int shift) {
    int idx = blockIdx.x * blockDim.x + threadIdx.x;
    int total = E << shift;
    if (idx >= total) return;
    int e = idx >> shift;
    int c = idx & ((1 << shift) - 1);
    int D4 = 1 << shift;
    int s = ei[e];
    int d = ei[E + e];
    float4 v = __ldg(x + (long long)s * D4 + c);
    float* p = agg + (((long long)d * D4 + c) << 2);
    asm volatile("red.global.add.v4.f32 [%0], {%1,%2,%3,%4};"
                 :: "l"(p), "f"(v.x), "f"(v.y), "f"(v.z), "f"(v.w)
                 : "memory");
}

// ---------------------------------------------------------------------------
// TF32 tensor-core GEMM:  C[M,Ncol] = op(Aeff @ W + bias)
//   Aeff = COMBINE ? (1+eps)*A + A2 : A
//   BM=128, BN=64, BK=32; 256 threads, 8 warps (4M x 2N), 32x32 warp tile.
//   mma.sync.aligned.m16n8k8.row.col.f32.tf32.tf32.f32
//   Smem rows have stride 36 -> fragment LDS hits (4r+c) mod 32: conflict-free.
// ---------------------------------------------------------------------------
__device__ __forceinline__ uint32_t f2tf(float f) {
    uint32_t u;
    asm("cvt.rna.tf32.f32 %0, %1;" : "=r"(u) : "f"(f));
    return u;
}

__device__ __forceinline__ void mma8(float* c, const uint32_t* a, const uint32_t* b) {
    asm volatile(
        "mma.sync.aligned.m16n8k8.row.col.f32.tf32.tf32.f32 "
        "{%0,%1,%2,%3}, {%4,%5,%6,%7}, {%8,%9}, {%0,%1,%2,%3};\n"
        : "+f"(c[0]), "+f"(c[1]), "+f"(c[2]), "+f"(c[3])
        : "r"(a[0]), "r"(a[1]), "r"(a[2]), "r"(a[3]), "r"(b[0]), "r"(b[1]));
}

template<bool COMBINE, bool RELU>
__global__ __launch_bounds__(256, 2)
void gemm_tf32(const float* __restrict__ A,
               const float* __restrict__ A2,
               const float* __restrict__ epsp,
               const float* __restrict__ W,
               const float* __restrict__ bias,
               float* __restrict__ C,
               int M, int K, int Ncol) {
    constexpr int BM = 128, BN = 64, BK = 32, SA = 36;
    __shared__ __align__(16) uint32_t As[BM][SA];   // [m][k]
    __shared__ __align__(16) uint32_t Bs[BN][SA];   // [n][k]  (transposed on store)

    const int tid  = threadIdx.x;
    const int lane = tid & 31;
    const int warp = tid >> 5;
    const int wm   = warp >> 1;      // 0..3
    const int wn   = warp & 1;       // 0..1
    const int gid  = lane >> 2;      // 0..7
    const int tig  = lane & 3;       // 0..3

    const int row0 = blockIdx.x * BM;
    const int col0 = blockIdx.y * BN;

    float scale = 1.f;
    if (COMBINE) scale = 1.f + __ldg(epsp);

    // A loader mapping: 2 threads per row, 16 consecutive k each
    const int  row_a   = tid >> 1;            // 0..127
    const int  kseg    = (tid & 1) * 16;      // 0 or 16
    const bool rowa_ok = (row0 + row_a) < M;
    const float* Abase  = A  + (size_t)(row0 + row_a) * K + kseg;
    const float* A2base = COMBINE ? (A2 + (size_t)(row0 + row_a) * K + kseg) : A;

    // B loader mapping: one n-column per thread, 8 consecutive k each
    const int n_b = tid & 63;                 // 0..63
    const int kb  = (tid >> 6) * 8;           // 0,8,16,24
    const float* Wbase = W + col0 + n_b;

    float4 pa[4];
    float  pb[8];

    float acc[2][4][4];
    #pragma unroll
    for (int mt = 0; mt < 2; mt++)
        #pragma unroll
        for (int nt = 0; nt < 4; nt++)
            #pragma unroll
            for (int i = 0; i < 4; i++)
                acc[mt][nt][i] = 0.f;

    auto loadA = [&](int kc) {
        #pragma unroll
        for (int i = 0; i < 4; i++) {
            float4 v = make_float4(0.f, 0.f, 0.f, 0.f);
            if (rowa_ok) {
                v = *reinterpret_cast<const float4*>(Abase + kc + 4 * i);
                if (COMBINE) {
                    float4 g = *reinterpret_cast<const float4*>(A2base + kc + 4 * i);
                    v.x = fmaf(scale, v.x, g.x);
                    v.y = fmaf(scale, v.y, g.y);
                    v.z = fmaf(scale, v.z, g.z);
                    v.w = fmaf(scale, v.w, g.w);
                }
            }
            pa[i] = v;
        }
    };
    auto loadB = [&](int kc) {
        #pragma unroll
        for (int i = 0; i < 8; i++)
            pb[i] = __ldg(Wbase + (size_t)(kc + kb + i) * Ncol);
    };
    auto storeA = [&]() {
        #pragma unroll
        for (int i = 0; i < 4; i++) {
            uint4 u;
            u.x = f2tf(pa[i].x); u.y = f2tf(pa[i].y);
            u.z = f2tf(pa[i].z); u.w = f2tf(pa[i].w);
            *reinterpret_cast<uint4*>(&As[row_a][kseg + 4 * i]) = u;
        }
    };
    auto storeB = [&]() {
        uint4 u0, u1;
        u0.x = f2tf(pb[0]); u0.y = f2tf(pb[1]); u0.z = f2tf(pb[2]); u0.w = f2tf(pb[3]);
        u1.x = f2tf(pb[4]); u1.y = f2tf(pb[5]); u1.z = f2tf(pb[6]); u1.w = f2tf(pb[7]);
        *reinterpret_cast<uint4*>(&Bs[n_b][kb])     = u0;
        *reinterpret_cast<uint4*>(&Bs[n_b][kb + 4]) = u1;
    };
    auto compute = [&]() {
        #pragma unroll
        for (int ks = 0; ks < 4; ks++) {
            const int kk = ks * 8;
            uint32_t af[2][4];
            #pragma unroll
            for (int mt = 0; mt < 2; mt++) {
                int r = wm * 32 + mt * 16 + gid;
                af[mt][0] = As[r    ][kk + tig];
                af[mt][1] = As[r + 8][kk + tig];
                af[mt][2] = As[r    ][kk + tig + 4];
                af[mt][3] = As[r + 8][kk + tig + 4];
            }
            uint32_t bf[4][2];
            #pragma unroll
            for (int nt = 0; nt < 4; nt++) {
                int n = wn * 32 + nt * 8 + gid;
                bf[nt][0] = Bs[n][kk + tig];
                bf[nt][1] = Bs[n][kk + tig + 4];
            }
            #pragma unroll
            for (int mt = 0; mt < 2; mt++)
                #pragma unroll
                for (int nt = 0; nt < 4; nt++)
                    mma8(acc[mt][nt], af[mt], bf[nt]);
        }
    };

    const int NC = K / BK;
    loadA(0); loadB(0);
    storeA(); storeB();
    __syncthreads();
    for (int c = 0;; c++) {
        if (c + 1 < NC) { loadA((c + 1) * BK); loadB((c + 1) * BK); }
        compute();
        if (c + 1 == NC) break;
        __syncthreads();
        storeA(); storeB();
        __syncthreads();
    }

    // ---- epilogue ----
    #pragma unroll
    for (int mt = 0; mt < 2; mt++) {
        #pragma unroll
        for (int nt = 0; nt < 4; nt++) {
            int col = col0 + wn * 32 + nt * 8 + 2 * tig;
            float b0 = __ldg(bias + col);
            float b1 = __ldg(bias + col + 1);
            int r = row0 + wm * 32 + mt * 16 + gid;
            float v0 = acc[mt][nt][0] + b0;
            float v1 = acc[mt][nt][1] + b1;
            float v2 = acc[mt][nt][2] + b0;
            float v3 = acc[mt][nt][3] + b1;
            if (RELU) {
                v0 = fmaxf(v0, 0.f); v1 = fmaxf(v1, 0.f);
                v2 = fmaxf(v2, 0.f); v3 = fmaxf(v3, 0.f);
            }
            if (r < M) {
                float2 o = make_float2(v0, v1);
                *reinterpret_cast<float2*>(C + (size_t)r * Ncol + col) = o;
            }
            if (r + 8 < M) {
                float2 o = make_float2(v2, v3);
                *reinterpret_cast<float2*>(C + (size_t)(r + 8) * Ncol + col) = o;
            }
        }
    }
}

// ---------------------------------------------------------------------------
// Launch
// ---------------------------------------------------------------------------
extern "C" void kernel_launch(void* const* d_in, const int* in_sizes, int n_in,
                              void* d_out, int out_size) {
    const float* x    = (const float*)d_in[0];
    const void*  eiRaw= d_in[1];
    const float* eps0 = (const float*)d_in[2];
    const float* W1_0 = (const float*)d_in[3];
    const float* b1_0 = (const float*)d_in[4];
    const float* W2_0 = (const float*)d_in[5];
    const float* b2_0 = (const float*)d_in[6];
    const float* eps1 = (const float*)d_in[7];
    const float* W1_1 = (const float*)d_in[8];
    const float* b1_1 = (const float*)d_in[9];
    const float* W2_1 = (const float*)d_in[10];
    const float* b2_1 = (const float*)d_in[11];
    const float* Wo   = (const float*)d_in[12];
    const float* bo   = (const float*)d_in[13];
    float*       out  = (float*)d_out;

    const int two_e = in_sizes[1];
    const int E     = two_e / 2;

    float *agg, *t1, *h0;
    int   *ei;
    cudaGetSymbolAddress((void**)&agg, g_agg);
    cudaGetSymbolAddress((void**)&t1,  g_t1);
    cudaGetSymbolAddress((void**)&h0,  g_h0);
    cudaGetSymbolAddress((void**)&ei,  g_ei32);

    // ---- normalize edge index to int32 ----
    int nscan = two_e < 128 ? two_e : 128;
    detect_kernel<<<1, 32>>>(eiRaw, nscan);
    convert_kernel<<<(two_e + 255) / 256, 256>>>(eiRaw, ei, two_e);

    dim3 blk(256);
    dim3 gH((N_NODES + 127) / 128, D_HID / 64);   // 391 x 4
    dim3 gO((N_NODES + 127) / 128, D_IN  / 64);   // 391 x 2

    // ---- layer 0 (D_IN -> D_HID) ----
    {
        int n4 = N_NODES * D_IN / 4;
        zero_kernel<<<(n4 + 255) / 256, 256>>>((float4*)agg, n4);
        long long tot = (long long)E << 5;
        scatter_kernel<<<(int)((tot + 255) / 256), 256>>>((const float4*)x, ei, agg, E, 5);
    }
    gemm_tf32<true,  true ><<<gH, blk>>>(x,  agg,  eps0, W1_0, b1_0, t1, N_NODES, D_IN,  D_HID);
    gemm_tf32<false, false><<<gH, blk>>>(t1, nullptr, nullptr, W2_0, b2_0, h0, N_NODES, D_HID, D_HID);

    // ---- layer 1 (D_HID -> D_HID) ----
    {
        int n4 = N_NODES * D_HID / 4;
        zero_kernel<<<(n4 + 255) / 256, 256>>>((float4*)agg, n4);
        long long tot = (long long)E << 6;
        scatter_kernel<<<(int)((tot + 255) / 256), 256>>>((const float4*)h0, ei, agg, E, 6);
    }
    gemm_tf32<true,  true ><<<gH, blk>>>(h0, agg,  eps1, W1_1, b1_1, t1, N_NODES, D_HID, D_HID);
    // reuse agg buffer as h1
    gemm_tf32<false, false><<<gH, blk>>>(t1, nullptr, nullptr, W2_1, b2_1, agg, N_NODES, D_HID, D_HID);

    // ---- fc_out (D_HID -> D_IN) ----
    gemm_tf32<false, false><<<gO, blk>>>(agg, nullptr, nullptr, Wo, bo, out, N_NODES, D_HID, D_IN);
}

// round 4
// speedup vs baseline: 2.8749x; 1.1747x over previous
#include <cuda_runtime.h>
#include <cuda_bf16.h>
#include <cstdint>
#include <cstddef>

#define N_NODES 50000
#define D_IN    128
#define D_HID   256
#define E_MAX   800000

// Scratch (allocation-free rule: __device__ globals)
__device__ float g_agg[N_NODES * D_HID];
__device__ float g_t1 [N_NODES * D_HID];
__device__ float g_h0 [N_NODES * D_HID];
__device__ int   g_ei32[2 * E_MAX];
__device__ int   g_mode;            // 1 = input is int64, 0 = int32
__device__ int   g_deg [N_NODES];
__device__ int   g_cur [N_NODES];
__device__ int   g_off [N_NODES + 1];
__device__ int   g_esrc[E_MAX];

// ---------------------------------------------------------------------------
// Edge-index dtype detect + convert
// ---------------------------------------------------------------------------
__global__ void detect_kernel(const void* __restrict__ ei_raw, int nscan) {
    if (threadIdx.x == 0 && blockIdx.x == 0) {
        const long long* p = (const long long*)ei_raw;
        int is64 = 1;
        for (int i = 0; i < nscan; i++) {
            long long v = p[i];
            if (v < 0 || v >= N_NODES) { is64 = 0; break; }
        }
        g_mode = is64;
    }
}

__global__ void convert_kernel(const void* __restrict__ ei_raw,
                               int* __restrict__ out, int n) {
    int i = blockIdx.x * blockDim.x + threadIdx.x;
    if (i >= n) return;
    if (g_mode) out[i] = (int)((const long long*)ei_raw)[i];
    else        out[i] = ((const int*)ei_raw)[i];
}

// ---------------------------------------------------------------------------
// CSR build: degree histogram -> prefix scan -> bucket fill
// ---------------------------------------------------------------------------
__global__ void zero_int_kernel(int* __restrict__ p, int n) {
    int i = blockIdx.x * blockDim.x + threadIdx.x;
    if (i < n) p[i] = 0;
}

__global__ void hist_kernel(const int* __restrict__ ei, int* __restrict__ deg, int E) {
    int e = blockIdx.x * blockDim.x + threadIdx.x;
    if (e >= E) return;
    atomicAdd(&deg[ei[E + e]], 1);
}

__global__ __launch_bounds__(1024)
void scan_kernel(const int* __restrict__ deg, int* __restrict__ off,
                 int* __restrict__ cursor, int n) {
    __shared__ int part[1024];
    int t = threadIdx.x;
    const int SEG = (n + 1023) / 1024;
    int lo = t * SEG;
    int hi = lo + SEG; if (hi > n) hi = n;
    int s = 0;
    for (int i = lo; i < hi; i++) s += deg[i];
    part[t] = s;
    __syncthreads();
    for (int d = 1; d < 1024; d <<= 1) {
        int v = (t >= d) ? part[t - d] : 0;
        __syncthreads();
        part[t] += v;
        __syncthreads();
    }
    int run = (t == 0) ? 0 : part[t - 1];
    for (int i = lo; i < hi; i++) {
        cursor[i] = run;          // exclusive prefix = bucket start
        run += deg[i];
        off[i + 1] = run;
    }
    if (t == 0) off[0] = 0;
}

__global__ void fill_kernel(const int* __restrict__ ei, int* __restrict__ cursor,
                            int* __restrict__ esrc, int E) {
    int e = blockIdx.x * blockDim.x + threadIdx.x;
    if (e >= E) return;
    int src = ei[e];
    int dst = ei[E + e];
    int pos = atomicAdd(&cursor[dst], 1);
    esrc[pos] = src;
}

// ---------------------------------------------------------------------------
// CSR gather-aggregate: one warp per node, acc in regs, single write.
// D4 = row width in float4 (32 for D=128, 64 for D=256).
// Degree-0 nodes write zeros -> no separate zero-fill needed.
// ---------------------------------------------------------------------------
__device__ __forceinline__ void f4add(float4& a, const float4& b) {
    a.x += b.x; a.y += b.y; a.z += b.z; a.w += b.w;
}

template<int D4>
__global__ __launch_bounds__(256)
void gather_kernel(const float4* __restrict__ x,
                   const int* __restrict__ off,
                   const int* __restrict__ esrc,
                   float4* __restrict__ agg) {
    int node = blockIdx.x * 8 + (threadIdx.x >> 5);
    if (node >= N_NODES) return;
    int lane = threadIdx.x & 31;
    int s = off[node], e = off[node + 1];

    float4 a0 = make_float4(0.f, 0.f, 0.f, 0.f);
    float4 a1 = make_float4(0.f, 0.f, 0.f, 0.f);

    int i = s;
    for (; i + 1 < e; i += 2) {
        int s0 = esrc[i], s1 = esrc[i + 1];
        const float4* r0 = x + (size_t)s0 * D4;
        const float4* r1 = x + (size_t)s1 * D4;
        float4 v0 = __ldg(r0 + lane);
        float4 v1 = __ldg(r1 + lane);
        f4add(a0, v0); f4add(a0, v1);
        if (D4 == 64) {
            float4 w0 = __ldg(r0 + lane + 32);
            float4 w1 = __ldg(r1 + lane + 32);
            f4add(a1, w0); f4add(a1, w1);
        }
    }
    if (i < e) {
        const float4* r0 = x + (size_t)esrc[i] * D4;
        f4add(a0, __ldg(r0 + lane));
        if (D4 == 64) f4add(a1, __ldg(r0 + lane + 32));
    }
    agg[(size_t)node * D4 + lane] = a0;
    if (D4 == 64) agg[(size_t)node * D4 + lane + 32] = a1;
}

// ---------------------------------------------------------------------------
// TF32 tensor-core GEMM, smem double-buffered (1 sync per K-chunk).
//   C[M,Ncol] = op(Aeff @ W + bias), Aeff = COMBINE ? (1+eps)*A + A2 : A
//   BM=128, BN=64, BK=32; 256 threads, 8 warps (4M x 2N), 32x32 warp tile.
// ---------------------------------------------------------------------------
__device__ __forceinline__ uint32_t f2tf(float f) {
    uint32_t u;
    asm("cvt.rna.tf32.f32 %0, %1;" : "=r"(u) : "f"(f));
    return u;
}

__device__ __forceinline__ void mma8(float* c, const uint32_t* a, const uint32_t* b) {
    asm volatile(
        "mma.sync.aligned.m16n8k8.row.col.f32.tf32.tf32.f32 "
        "{%0,%1,%2,%3}, {%4,%5,%6,%7}, {%8,%9}, {%0,%1,%2,%3};\n"
        : "+f"(c[0]), "+f"(c[1]), "+f"(c[2]), "+f"(c[3])
        : "r"(a[0]), "r"(a[1]), "r"(a[2]), "r"(a[3]), "r"(b[0]), "r"(b[1]));
}

#define GEMM_BM 128
#define GEMM_BN 64
#define GEMM_BK 32
#define GEMM_SA 36
#define GEMM_SMEM_BYTES ((2 * GEMM_BM + 2 * GEMM_BN) * GEMM_SA * 4)

template<bool COMBINE, bool RELU>
__global__ __launch_bounds__(256, 2)
void gemm_tf32(const float* __restrict__ A,
               const float* __restrict__ A2,
               const float* __restrict__ epsp,
               const float* __restrict__ W,
               const float* __restrict__ bias,
               float* __restrict__ C,
               int M, int K, int Ncol) {
    constexpr int BM = GEMM_BM, BN = GEMM_BN, BK = GEMM_BK, SA = GEMM_SA;
    extern __shared__ uint32_t dsm[];
    uint32_t (*AsBuf)[SA] = (uint32_t (*)[SA])dsm;            // [2*BM][SA]
    uint32_t (*BsBuf)[SA] = AsBuf + 2 * BM;                   // [2*BN][SA]

    const int tid  = threadIdx.x;
    const int lane = tid & 31;
    const int warp = tid >> 5;
    const int wm   = warp >> 1;
    const int wn   = warp & 1;
    const int gid  = lane >> 2;
    const int tig  = lane & 3;

    const int row0 = blockIdx.x * BM;
    const int col0 = blockIdx.y * BN;

    float scale = 1.f;
    if (COMBINE) scale = 1.f + __ldg(epsp);

    const int  row_a   = tid >> 1;
    const int  kseg    = (tid & 1) * 16;
    const bool rowa_ok = (row0 + row_a) < M;
    const float* Abase  = A  + (size_t)(row0 + row_a) * K + kseg;
    const float* A2base = COMBINE ? (A2 + (size_t)(row0 + row_a) * K + kseg) : A;

    const int n_b = tid & 63;
    const int kb  = (tid >> 6) * 8;
    const float* Wbase = W + col0 + n_b;

    float4 pa[4];
    float  pb[8];

    float acc[2][4][4];
    #pragma unroll
    for (int mt = 0; mt < 2; mt++)
        #pragma unroll
        for (int nt = 0; nt < 4; nt++)
            #pragma unroll
            for (int i = 0; i < 4; i++)
                acc[mt][nt][i] = 0.f;

    auto loadA = [&](int kc) {
        #pragma unroll
        for (int i = 0; i < 4; i++) {
            float4 v = make_float4(0.f, 0.f, 0.f, 0.f);
            if (rowa_ok) {
                v = *reinterpret_cast<const float4*>(Abase + kc + 4 * i);
                if (COMBINE) {
                    float4 g = *reinterpret_cast<const float4*>(A2base + kc + 4 * i);
                    v.x = fmaf(scale, v.x, g.x);
                    v.y = fmaf(scale, v.y, g.y);
                    v.z = fmaf(scale, v.z, g.z);
                    v.w = fmaf(scale, v.w, g.w);
                }
            }
            pa[i] = v;
        }
    };
    auto loadB = [&](int kc) {
        #pragma unroll
        for (int i = 0; i < 8; i++)
            pb[i] = __ldg(Wbase + (size_t)(kc + kb + i) * Ncol);
    };
    auto storeA = [&](int buf) {
        uint32_t (*As)[SA] = AsBuf + buf * BM;
        #pragma unroll
        for (int i = 0; i < 4; i++) {
            uint4 u;
            u.x = f2tf(pa[i].x); u.y = f2tf(pa[i].y);
            u.z = f2tf(pa[i].z); u.w = f2tf(pa[i].w);
            *reinterpret_cast<uint4*>(&As[row_a][kseg + 4 * i]) = u;
        }
    };
    auto storeB = [&](int buf) {
        uint32_t (*Bs)[SA] = BsBuf + buf * BN;
        uint4 u0, u1;
        u0.x = f2tf(pb[0]); u0.y = f2tf(pb[1]); u0.z = f2tf(pb[2]); u0.w = f2tf(pb[3]);
        u1.x = f2tf(pb[4]); u1.y = f2tf(pb[5]); u1.z = f2tf(pb[6]); u1.w = f2tf(pb[7]);
        *reinterpret_cast<uint4*>(&Bs[n_b][kb])     = u0;
        *reinterpret_cast<uint4*>(&Bs[n_b][kb + 4]) = u1;
    };
    auto compute = [&](int buf) {
        uint32_t (*As)[SA] = AsBuf + buf * BM;
        uint32_t (*Bs)[SA] = BsBuf + buf * BN;
        #pragma unroll
        for (int ks = 0; ks < 4; ks++) {
            const int kk = ks * 8;
            uint32_t af[2][4];
            #pragma unroll
            for (int mt = 0; mt < 2; mt++) {
                int r = wm * 32 + mt * 16 + gid;
                af[mt][0] = As[r    ][kk + tig];
                af[mt][1] = As[r + 8][kk + tig];
                af[mt][2] = As[r    ][kk + tig + 4];
                af[mt][3] = As[r + 8][kk + tig + 4];
            }
            uint32_t bf[4][2];
            #pragma unroll
            for (int nt = 0; nt < 4; nt++) {
                int n = wn * 32 + nt * 8 + gid;
                bf[nt][0] = Bs[n][kk + tig];
                bf[nt][1] = Bs[n][kk + tig + 4];
            }
            #pragma unroll
            for (int mt = 0; mt < 2; mt++)
                #pragma unroll
                for (int nt = 0; nt < 4; nt++)
                    mma8(acc[mt][nt], af[mt], bf[nt]);
        }
    };

    const int NC = K / BK;
    loadA(0); loadB(0);
    storeA(0); storeB(0);
    __syncthreads();
    if (NC > 1) { loadA(BK); loadB(BK); }

    for (int c = 0; c < NC; c++) {
        if (c + 1 < NC) { storeA((c + 1) & 1); storeB((c + 1) & 1); }
        if (c + 2 < NC) { loadA((c + 2) * BK); loadB((c + 2) * BK); }
        compute(c & 1);
        __syncthreads();
    }

    // ---- epilogue ----
    #pragma unroll
    for (int mt = 0; mt < 2; mt++) {
        #pragma unroll
        for (int nt = 0; nt < 4; nt++) {
            int col = col0 + wn * 32 + nt * 8 + 2 * tig;
            float b0 = __ldg(bias + col);
            float b1 = __ldg(bias + col + 1);
            int r = row0 + wm * 32 + mt * 16 + gid;
            float v0 = acc[mt][nt][0] + b0;
            float v1 = acc[mt][nt][1] + b1;
            float v2 = acc[mt][nt][2] + b0;
            float v3 = acc[mt][nt][3] + b1;
            if (RELU) {
                v0 = fmaxf(v0, 0.f); v1 = fmaxf(v1, 0.f);
                v2 = fmaxf(v2, 0.f); v3 = fmaxf(v3, 0.f);
            }
            if (r < M)
                *reinterpret_cast<float2*>(C + (size_t)r * Ncol + col) = make_float2(v0, v1);
            if (r + 8 < M)
                *reinterpret_cast<float2*>(C + (size_t)(r + 8) * Ncol + col) = make_float2(v2, v3);
        }
    }
}

// ---------------------------------------------------------------------------
// Launch
// ---------------------------------------------------------------------------
extern "C" void kernel_launch(void* const* d_in, const int* in_sizes, int n_in,
                              void* d_out, int out_size) {
    const float* x    = (const float*)d_in[0];
    const void*  eiRaw= d_in[1];
    const float* eps0 = (const float*)d_in[2];
    const float* W1_0 = (const float*)d_in[3];
    const float* b1_0 = (const float*)d_in[4];
    const float* W2_0 = (const float*)d_in[5];
    const float* b2_0 = (const float*)d_in[6];
    const float* eps1 = (const float*)d_in[7];
    const float* W1_1 = (const float*)d_in[8];
    const float* b1_1 = (const float*)d_in[9];
    const float* W2_1 = (const float*)d_in[10];
    const float* b2_1 = (const float*)d_in[11];
    const float* Wo   = (const float*)d_in[12];
    const float* bo   = (const float*)d_in[13];
    float*       out  = (float*)d_out;

    const int two_e = in_sizes[1];
    const int E     = two_e / 2;

    float *agg, *t1, *h0;
    int *ei, *deg, *cur, *off, *esrc;
    cudaGetSymbolAddress((void**)&agg,  g_agg);
    cudaGetSymbolAddress((void**)&t1,   g_t1);
    cudaGetSymbolAddress((void**)&h0,   g_h0);
    cudaGetSymbolAddress((void**)&ei,   g_ei32);
    cudaGetSymbolAddress((void**)&deg,  g_deg);
    cudaGetSymbolAddress((void**)&cur,  g_cur);
    cudaGetSymbolAddress((void**)&off,  g_off);
    cudaGetSymbolAddress((void**)&esrc, g_esrc);

    // allow >48KB dynamic smem for the GEMMs (idempotent)
    cudaFuncSetAttribute(gemm_tf32<true,  true >,
                         cudaFuncAttributeMaxDynamicSharedMemorySize, GEMM_SMEM_BYTES);
    cudaFuncSetAttribute(gemm_tf32<false, false>,
                         cudaFuncAttributeMaxDynamicSharedMemorySize, GEMM_SMEM_BYTES);

    // ---- normalize edge index to int32 ----
    int nscan = two_e < 128 ? two_e : 128;
    detect_kernel<<<1, 32>>>(eiRaw, nscan);
    convert_kernel<<<(two_e + 255) / 256, 256>>>(eiRaw, ei, two_e);

    // ---- build CSR (dst -> list of src), shared by both layers ----
    zero_int_kernel<<<(N_NODES + 255) / 256, 256>>>(deg, N_NODES);
    hist_kernel<<<(E + 255) / 256, 256>>>(ei, deg, E);
    scan_kernel<<<1, 1024>>>(deg, off, cur, N_NODES);
    fill_kernel<<<(E + 255) / 256, 256>>>(ei, cur, esrc, E);

    dim3 blk(256);
    dim3 gH((N_NODES + 127) / 128, D_HID / 64);
    dim3 gO((N_NODES + 127) / 128, D_IN  / 64);
    int  gGather = (N_NODES + 7) / 8;

    // ---- layer 0 (D_IN -> D_HID) ----
    gather_kernel<32><<<gGather, 256>>>((const float4*)x, off, esrc, (float4*)agg);
    gemm_tf32<true,  true ><<<gH, blk, GEMM_SMEM_BYTES>>>(x,  agg,  eps0, W1_0, b1_0, t1, N_NODES, D_IN,  D_HID);
    gemm_tf32<false, false><<<gH, blk, GEMM_SMEM_BYTES>>>(t1, nullptr, nullptr, W2_0, b2_0, h0, N_NODES, D_HID, D_HID);

    // ---- layer 1 (D_HID -> D_HID) ----
    gather_kernel<64><<<gGather, 256>>>((const float4*)h0, off, esrc, (float4*)agg);
    gemm_tf32<true,  true ><<<gH, blk, GEMM_SMEM_BYTES>>>(h0, agg,  eps1, W1_1, b1_1, t1, N_NODES, D_HID, D_HID);
    // reuse agg buffer as h1
    gemm_tf32<false, false><<<gH, blk, GEMM_SMEM_BYTES>>>(t1, nullptr, nullptr, W2_1, b2_1, agg, N_NODES, D_HID, D_HID);

    // ---- fc_out (D_HID -> D_IN) ----
    gemm_tf32<false, false><<<gO, blk, GEMM_SMEM_BYTES>>>(agg, nullptr, nullptr, Wo, bo, out, N_NODES, D_HID, D_IN);
}

// round 5
// speedup vs baseline: 4.0248x; 1.4000x over previous
#include <cuda_runtime.h>
#include <cstdint>
#include <cstddef>

#define N_NODES 50000
#define D_IN    128
#define D_HID   256
#define E_MAX   800000

// Scratch (allocation-free rule: __device__ globals)
__device__ float g_comb[N_NODES * D_HID];   // gather_combine output (also h1 home)
__device__ float g_t1 [N_NODES * D_HID];
__device__ float g_h0 [N_NODES * D_HID];
__device__ float g_wq [262144];             // tf32-quantized weights
__device__ int   g_ei32[2 * E_MAX];
__device__ int   g_mode;
__device__ int   g_deg [N_NODES];
__device__ int   g_cur [N_NODES];
__device__ int   g_off [N_NODES + 1];
__device__ int   g_esrc[E_MAX];

// ---------------------------------------------------------------------------
// helpers
// ---------------------------------------------------------------------------
__device__ __forceinline__ float qtf(float f) {
    uint32_t u;
    asm("cvt.rna.tf32.f32 %0, %1;" : "=r"(u) : "f"(f));
    return __uint_as_float(u);
}

__device__ __forceinline__ uint32_t smem_u32(const void* p) {
    uint32_t a;
    asm("{ .reg .u64 t; cvta.to.shared.u64 t, %1; cvt.u32.u64 %0, t; }"
        : "=r"(a) : "l"(p));
    return a;
}

__device__ __forceinline__ void cpa16(uint32_t dst, const void* src, int vbytes) {
    asm volatile("cp.async.cg.shared.global [%0], [%1], 16, %2;"
                 :: "r"(dst), "l"(src), "r"(vbytes));
}
__device__ __forceinline__ void cp_commit() {
    asm volatile("cp.async.commit_group;");
}
template<int NP>
__device__ __forceinline__ void cp_wait() {
    asm volatile("cp.async.wait_group %0;" :: "n"(NP));
}

__device__ __forceinline__ void mma8(float* c, const uint32_t* a, const uint32_t* b) {
    asm volatile(
        "mma.sync.aligned.m16n8k8.row.col.f32.tf32.tf32.f32 "
        "{%0,%1,%2,%3}, {%4,%5,%6,%7}, {%8,%9}, {%0,%1,%2,%3};\n"
        : "+f"(c[0]), "+f"(c[1]), "+f"(c[2]), "+f"(c[3])
        : "r"(a[0]), "r"(a[1]), "r"(a[2]), "r"(a[3]), "r"(b[0]), "r"(b[1]));
}

// ---------------------------------------------------------------------------
// Edge-index dtype detect + convert
// ---------------------------------------------------------------------------
__global__ void detect_kernel(const void* __restrict__ ei_raw, int nscan) {
    if (threadIdx.x == 0 && blockIdx.x == 0) {
        const long long* p = (const long long*)ei_raw;
        int is64 = 1;
        for (int i = 0; i < nscan; i++) {
            long long v = p[i];
            if (v < 0 || v >= N_NODES) { is64 = 0; break; }
        }
        g_mode = is64;
    }
}

__global__ void convert_kernel(const void* __restrict__ ei_raw,
                               int* __restrict__ out, int n) {
    int i = blockIdx.x * blockDim.x + threadIdx.x;
    if (i >= n) return;
    if (g_mode) out[i] = (int)((const long long*)ei_raw)[i];
    else        out[i] = ((const int*)ei_raw)[i];
}

// ---------------------------------------------------------------------------
// CSR build
// ---------------------------------------------------------------------------
__global__ void zero_int_kernel(int* __restrict__ p, int n) {
    int i = blockIdx.x * blockDim.x + threadIdx.x;
    if (i < n) p[i] = 0;
}

__global__ void hist_kernel(const int* __restrict__ ei, int* __restrict__ deg, int E) {
    int e = blockIdx.x * blockDim.x + threadIdx.x;
    if (e >= E) return;
    atomicAdd(&deg[ei[E + e]], 1);
}

__global__ __launch_bounds__(1024)
void scan_kernel(const int* __restrict__ deg, int* __restrict__ off,
                 int* __restrict__ cursor, int n) {
    __shared__ int part[1024];
    int t = threadIdx.x;
    const int SEG = (n + 1023) / 1024;
    int lo = t * SEG;
    int hi = lo + SEG; if (hi > n) hi = n;
    int s = 0;
    for (int i = lo; i < hi; i++) s += deg[i];
    part[t] = s;
    __syncthreads();
    for (int d = 1; d < 1024; d <<= 1) {
        int v = (t >= d) ? part[t - d] : 0;
        __syncthreads();
        part[t] += v;
        __syncthreads();
    }
    int run = (t == 0) ? 0 : part[t - 1];
    for (int i = lo; i < hi; i++) {
        cursor[i] = run;
        run += deg[i];
        off[i + 1] = run;
    }
    if (t == 0) off[0] = 0;
}

__global__ void fill_kernel(const int* __restrict__ ei, int* __restrict__ cursor,
                            int* __restrict__ esrc, int E) {
    int e = blockIdx.x * blockDim.x + threadIdx.x;
    if (e >= E) return;
    int src = ei[e];
    int dst = ei[E + e];
    int pos = atomicAdd(&cursor[dst], 1);
    esrc[pos] = src;
}

// ---------------------------------------------------------------------------
// Weight pre-quantization (f32 -> tf32-rounded f32)
// ---------------------------------------------------------------------------
__global__ void quantw_kernel(const float* __restrict__ src, float* __restrict__ dst, int n) {
    int i = blockIdx.x * blockDim.x + threadIdx.x;
    if (i < n) dst[i] = qtf(src[i]);
}

// ---------------------------------------------------------------------------
// Fused gather + GIN combine: out[node] = tf32( (1+eps)*x[node] + sum_{s in N(node)} x[s] )
// One warp per node; D4 = row width in float4.
// ---------------------------------------------------------------------------
__device__ __forceinline__ void f4add(float4& a, const float4& b) {
    a.x += b.x; a.y += b.y; a.z += b.z; a.w += b.w;
}
__device__ __forceinline__ float4 q4(float4 v) {
    return make_float4(qtf(v.x), qtf(v.y), qtf(v.z), qtf(v.w));
}

template<int D4>
__global__ __launch_bounds__(256)
void gather_combine(const float4* __restrict__ x,
                    const int* __restrict__ off,
                    const int* __restrict__ esrc,
                    const float* __restrict__ epsp,
                    float4* __restrict__ out) {
    int node = blockIdx.x * 8 + (threadIdx.x >> 5);
    if (node >= N_NODES) return;
    int lane = threadIdx.x & 31;
    float scale = 1.f + __ldg(epsp);
    int s = off[node], e = off[node + 1];

    float4 a0 = make_float4(0.f, 0.f, 0.f, 0.f);
    float4 a1 = make_float4(0.f, 0.f, 0.f, 0.f);

    int i = s;
    for (; i + 1 < e; i += 2) {
        const float4* r0 = x + (size_t)esrc[i]     * D4;
        const float4* r1 = x + (size_t)esrc[i + 1] * D4;
        f4add(a0, __ldg(r0 + lane));
        f4add(a0, __ldg(r1 + lane));
        if (D4 == 64) {
            f4add(a1, __ldg(r0 + lane + 32));
            f4add(a1, __ldg(r1 + lane + 32));
        }
    }
    if (i < e) {
        const float4* r0 = x + (size_t)esrc[i] * D4;
        f4add(a0, __ldg(r0 + lane));
        if (D4 == 64) f4add(a1, __ldg(r0 + lane + 32));
    }
    // self term
    {
        const float4* sp = x + (size_t)node * D4;
        float4 v = __ldg(sp + lane);
        a0.x = fmaf(scale, v.x, a0.x);
        a0.y = fmaf(scale, v.y, a0.y);
        a0.z = fmaf(scale, v.z, a0.z);
        a0.w = fmaf(scale, v.w, a0.w);
        if (D4 == 64) {
            float4 w = __ldg(sp + lane + 32);
            a1.x = fmaf(scale, w.x, a1.x);
            a1.y = fmaf(scale, w.y, a1.y);
            a1.z = fmaf(scale, w.z, a1.z);
            a1.w = fmaf(scale, w.w, a1.w);
        }
    }
    out[(size_t)node * D4 + lane] = q4(a0);
    if (D4 == 64) out[(size_t)node * D4 + lane + 32] = q4(a1);
}

// ---------------------------------------------------------------------------
// TF32 GEMM, cp.async double-buffered. Inputs must already be tf32-rounded.
//   C = op(A @ W + bias);  BM=128, BN=128, BK=32; 256 thr, 8 warps (4m x 2n).
//   A smem [m][k] stride 36 (conflict-free); B smem [k][n] stride 136.
// ---------------------------------------------------------------------------
#define SA 36
#define SB 136
#define ASTAGE (128 * SA)          // words per A stage
#define BSTAGE (32  * SB)          // words per B stage
#define GEMM_SMEM_BYTES ((2 * ASTAGE + 2 * BSTAGE) * 4)

template<bool RELU, bool QUANT>
__global__ __launch_bounds__(256, 2)
void gemm_cp(const float* __restrict__ A,
             const float* __restrict__ W,
             const float* __restrict__ bias,
             float* __restrict__ C,
             int M, int K, int Ncol) {
    extern __shared__ float dsm[];
    float* Abuf = dsm;
    float* Bbuf = dsm + 2 * ASTAGE;
    const uint32_t sA = smem_u32(Abuf);
    const uint32_t sB = smem_u32(Bbuf);

    const int tid  = threadIdx.x;
    const int lane = tid & 31;
    const int warp = tid >> 5;
    const int wm   = warp >> 1;        // 0..3
    const int wn   = warp & 1;         // 0..1
    const int gid  = lane >> 2;        // 0..7
    const int tig  = lane & 3;         // 0..3

    const int row0 = blockIdx.x * 128;
    const int col0 = blockIdx.y * 128;

    float acc[2][8][4];
    #pragma unroll
    for (int mt = 0; mt < 2; mt++)
        #pragma unroll
        for (int nt = 0; nt < 8; nt++)
            #pragma unroll
            for (int i = 0; i < 4; i++)
                acc[mt][nt][i] = 0.f;

    auto issue = [&](int c) {
        const int k0  = c * 32;
        const int buf = c & 1;
        const uint32_t abase = sA + buf * ASTAGE * 4;
        #pragma unroll
        for (int i = 0; i < 4; i++) {
            int chunk = tid + 256 * i;          // 0..1023
            int row = chunk >> 3, c16 = chunk & 7;
            bool ok = (row0 + row) < M;
            const float* src = ok ? (A + (size_t)(row0 + row) * K + k0 + c16 * 4) : A;
            cpa16(abase + (row * SA + c16 * 4) * 4, src, ok ? 16 : 0);
        }
        const uint32_t bbase = sB + buf * BSTAGE * 4;
        #pragma unroll
        for (int i = 0; i < 4; i++) {
            int chunk = tid + 256 * i;          // 0..1023
            int kr = chunk >> 5, n16 = chunk & 31;
            const float* src = W + (size_t)(k0 + kr) * Ncol + col0 + n16 * 4;
            cpa16(bbase + (kr * SB + n16 * 4) * 4, src, 16);
        }
    };

    auto compute = [&](int buf) {
        const float* As = Abuf + buf * ASTAGE;
        const float* Bs = Bbuf + buf * BSTAGE;
        #pragma unroll
        for (int ks = 0; ks < 4; ks++) {
            const int kk = ks * 8;
            uint32_t af[2][4];
            #pragma unroll
            for (int mt = 0; mt < 2; mt++) {
                int r = wm * 32 + mt * 16 + gid;
                af[mt][0] = __float_as_uint(As[ r      * SA + kk + tig    ]);
                af[mt][1] = __float_as_uint(As[(r + 8) * SA + kk + tig    ]);
                af[mt][2] = __float_as_uint(As[ r      * SA + kk + tig + 4]);
                af[mt][3] = __float_as_uint(As[(r + 8) * SA + kk + tig + 4]);
            }
            uint32_t bf[8][2];
            #pragma unroll
            for (int nt = 0; nt < 8; nt++) {
                int n = wn * 64 + nt * 8 + gid;
                bf[nt][0] = __float_as_uint(Bs[(kk + tig)     * SB + n]);
                bf[nt][1] = __float_as_uint(Bs[(kk + tig + 4) * SB + n]);
            }
            #pragma unroll
            for (int mt = 0; mt < 2; mt++)
                #pragma unroll
                for (int nt = 0; nt < 8; nt++)
                    mma8(acc[mt][nt], af[mt], bf[nt]);
        }
    };

    const int NC = K / 32;
    issue(0); cp_commit();
    issue(1); cp_commit();

    for (int c = 0; c < NC; c++) {
        cp_wait<1>();
        __syncthreads();
        compute(c & 1);
        __syncthreads();
        if (c + 2 < NC) issue(c + 2);
        cp_commit();                 // empty group at tail keeps counting uniform
    }

    // ---- epilogue ----
    #pragma unroll
    for (int mt = 0; mt < 2; mt++) {
        #pragma unroll
        for (int nt = 0; nt < 8; nt++) {
            int col = col0 + wn * 64 + nt * 8 + 2 * tig;
            float b0 = __ldg(bias + col);
            float b1 = __ldg(bias + col + 1);
            int r = row0 + wm * 32 + mt * 16 + gid;
            float v0 = acc[mt][nt][0] + b0;
            float v1 = acc[mt][nt][1] + b1;
            float v2 = acc[mt][nt][2] + b0;
            float v3 = acc[mt][nt][3] + b1;
            if (RELU) {
                v0 = fmaxf(v0, 0.f); v1 = fmaxf(v1, 0.f);
                v2 = fmaxf(v2, 0.f); v3 = fmaxf(v3, 0.f);
            }
            if (QUANT) {
                v0 = qtf(v0); v1 = qtf(v1); v2 = qtf(v2); v3 = qtf(v3);
            }
            if (r < M)
                *reinterpret_cast<float2*>(C + (size_t)r * Ncol + col) = make_float2(v0, v1);
            if (r + 8 < M)
                *reinterpret_cast<float2*>(C + (size_t)(r + 8) * Ncol + col) = make_float2(v2, v3);
        }
    }
}

// ---------------------------------------------------------------------------
// Launch
// ---------------------------------------------------------------------------
extern "C" void kernel_launch(void* const* d_in, const int* in_sizes, int n_in,
                              void* d_out, int out_size) {
    const float* x    = (const float*)d_in[0];
    const void*  eiRaw= d_in[1];
    const float* eps0 = (const float*)d_in[2];
    const float* W1_0 = (const float*)d_in[3];
    const float* b1_0 = (const float*)d_in[4];
    const float* W2_0 = (const float*)d_in[5];
    const float* b2_0 = (const float*)d_in[6];
    const float* eps1 = (const float*)d_in[7];
    const float* W1_1 = (const float*)d_in[8];
    const float* b1_1 = (const float*)d_in[9];
    const float* W2_1 = (const float*)d_in[10];
    const float* b2_1 = (const float*)d_in[11];
    const float* Wo   = (const float*)d_in[12];
    const float* bo   = (const float*)d_in[13];
    float*       out  = (float*)d_out;

    const int two_e = in_sizes[1];
    const int E     = two_e / 2;

    float *comb, *t1, *h0, *wq;
    int *ei, *deg, *cur, *off, *esrc;
    cudaGetSymbolAddress((void**)&comb, g_comb);
    cudaGetSymbolAddress((void**)&t1,   g_t1);
    cudaGetSymbolAddress((void**)&h0,   g_h0);
    cudaGetSymbolAddress((void**)&wq,   g_wq);
    cudaGetSymbolAddress((void**)&ei,   g_ei32);
    cudaGetSymbolAddress((void**)&deg,  g_deg);
    cudaGetSymbolAddress((void**)&cur,  g_cur);
    cudaGetSymbolAddress((void**)&off,  g_off);
    cudaGetSymbolAddress((void**)&esrc, g_esrc);

    float* W1_0q = wq;                   // 128*256 = 32768
    float* W2_0q = wq + 32768;           // 256*256 = 65536
    float* W1_1q = wq + 98304;           // 65536
    float* W2_1q = wq + 163840;          // 65536
    float* Woq   = wq + 229376;          // 256*128 = 32768

    cudaFuncSetAttribute(gemm_cp<true,  true >,
                         cudaFuncAttributeMaxDynamicSharedMemorySize, GEMM_SMEM_BYTES);
    cudaFuncSetAttribute(gemm_cp<false, false>,
                         cudaFuncAttributeMaxDynamicSharedMemorySize, GEMM_SMEM_BYTES);
    cudaFuncSetAttribute(gemm_cp<false, true >,
                         cudaFuncAttributeMaxDynamicSharedMemorySize, GEMM_SMEM_BYTES);

    // ---- normalize edge index ----
    int nscan = two_e < 128 ? two_e : 128;
    detect_kernel<<<1, 32>>>(eiRaw, nscan);
    convert_kernel<<<(two_e + 255) / 256, 256>>>(eiRaw, ei, two_e);

    // ---- CSR build ----
    zero_int_kernel<<<(N_NODES + 255) / 256, 256>>>(deg, N_NODES);
    hist_kernel<<<(E + 255) / 256, 256>>>(ei, deg, E);
    scan_kernel<<<1, 1024>>>(deg, off, cur, N_NODES);
    fill_kernel<<<(E + 255) / 256, 256>>>(ei, cur, esrc, E);

    // ---- pre-quantize weights to tf32 ----
    quantw_kernel<<<(32768 + 255) / 256, 256>>>(W1_0, W1_0q, 32768);
    quantw_kernel<<<(65536 + 255) / 256, 256>>>(W2_0, W2_0q, 65536);
    quantw_kernel<<<(65536 + 255) / 256, 256>>>(W1_1, W1_1q, 65536);
    quantw_kernel<<<(65536 + 255) / 256, 256>>>(W2_1, W2_1q, 65536);
    quantw_kernel<<<(32768 + 255) / 256, 256>>>(Wo,   Woq,   32768);

    dim3 blk(256);
    dim3 gH((N_NODES + 127) / 128, 2);   // Ncol=256
    dim3 gO((N_NODES + 127) / 128, 1);   // Ncol=128
    int  gGather = (N_NODES + 7) / 8;

    // ---- layer 0 ----
    gather_combine<32><<<gGather, 256>>>((const float4*)x, off, esrc, eps0, (float4*)comb);
    gemm_cp<true,  true ><<<gH, blk, GEMM_SMEM_BYTES>>>(comb, W1_0q, b1_0, t1, N_NODES, D_IN,  D_HID);
    gemm_cp<false, false><<<gH, blk, GEMM_SMEM_BYTES>>>(t1,   W2_0q, b2_0, h0, N_NODES, D_HID, D_HID);

    // ---- layer 1 ----
    gather_combine<64><<<gGather, 256>>>((const float4*)h0, off, esrc, eps1, (float4*)comb);
    gemm_cp<true,  true ><<<gH, blk, GEMM_SMEM_BYTES>>>(comb, W1_1q, b1_1, t1, N_NODES, D_HID, D_HID);
    gemm_cp<false, true ><<<gH, blk, GEMM_SMEM_BYTES>>>(t1,   W2_1q, b2_1, h0, N_NODES, D_HID, D_HID); // h1

    // ---- fc_out ----
    gemm_cp<false, false><<<gO, blk, GEMM_SMEM_BYTES>>>(h0, Woq, bo, out, N_NODES, D_HID, D_IN);
}

// round 7
// speedup vs baseline: 5.0240x; 1.2483x over previous
#include <cuda_runtime.h>
#include <cstdint>
#include <cstddef>

#define N_NODES 50000
#define D_IN    128
#define D_HID   256
#define E_MAX   800000

// Scratch (allocation-free rule: __device__ globals)
__device__ float g_comb[N_NODES * D_HID];
__device__ float g_t1 [N_NODES * D_HID];
__device__ float g_h0 [N_NODES * D_HID];
__device__ float g_wq [262144];             // tf32-quantized weights (R5 layout, no transpose)
__device__ int   g_mode;
__device__ int   g_deg [N_NODES];
__device__ int   g_cur [N_NODES];
__device__ int   g_off [N_NODES + 1];
__device__ int   g_esrc[E_MAX];
__device__ int   g_bsum[256];
__device__ int   g_boff[256];

// ---------------------------------------------------------------------------
// helpers
// ---------------------------------------------------------------------------
__device__ __forceinline__ float qtf(float f) {
    uint32_t u;
    asm("cvt.rna.tf32.f32 %0, %1;" : "=r"(u) : "f"(f));
    return __uint_as_float(u);
}

__device__ __forceinline__ uint32_t smem_u32(const void* p) {
    uint32_t a;
    asm("{ .reg .u64 t; cvta.to.shared.u64 t, %1; cvt.u32.u64 %0, t; }"
        : "=r"(a) : "l"(p));
    return a;
}

__device__ __forceinline__ void cpa16(uint32_t dst, const void* src, int vbytes) {
    asm volatile("cp.async.cg.shared.global [%0], [%1], 16, %2;"
                 :: "r"(dst), "l"(src), "r"(vbytes));
}
__device__ __forceinline__ void cp_commit() {
    asm volatile("cp.async.commit_group;");
}
template<int NP>
__device__ __forceinline__ void cp_wait() {
    asm volatile("cp.async.wait_group %0;" :: "n"(NP));
}

__device__ __forceinline__ void mma8(float* c, const uint32_t* a, const uint32_t* b) {
    asm volatile(
        "mma.sync.aligned.m16n8k8.row.col.f32.tf32.tf32.f32 "
        "{%0,%1,%2,%3}, {%4,%5,%6,%7}, {%8,%9}, {%0,%1,%2,%3};\n"
        : "+f"(c[0]), "+f"(c[1]), "+f"(c[2]), "+f"(c[3])
        : "r"(a[0]), "r"(a[1]), "r"(a[2]), "r"(a[3]), "r"(b[0]), "r"(b[1]));
}

// ---------------------------------------------------------------------------
// Edge-index dtype detect (harness may deliver int64 as int32)
// ---------------------------------------------------------------------------
__global__ void detect_kernel(const void* __restrict__ ei_raw, int nscan) {
    if (threadIdx.x == 0 && blockIdx.x == 0) {
        const long long* p = (const long long*)ei_raw;
        int is64 = 1;
        for (int i = 0; i < nscan; i++) {
            long long v = p[i];
            if (v < 0 || v >= N_NODES) { is64 = 0; break; }
        }
        g_mode = is64;
    }
}

__device__ __forceinline__ int edge_at(const void* raw, long long idx) {
    return g_mode ? (int)((const long long*)raw)[idx] : ((const int*)raw)[idx];
}

// ---------------------------------------------------------------------------
// CSR build (reads raw edge buffer directly; no int32 conversion pass)
// ---------------------------------------------------------------------------
__global__ void zero_int_kernel(int* __restrict__ p, int n) {
    int i = blockIdx.x * blockDim.x + threadIdx.x;
    if (i < n) p[i] = 0;
}

__global__ void hist_kernel(const void* __restrict__ raw, int* __restrict__ deg, int E) {
    int e = blockIdx.x * blockDim.x + threadIdx.x;
    if (e >= E) return;
    atomicAdd(&deg[edge_at(raw, (long long)E + e)], 1);
}

// Parallel scan of deg[0..N): phase 1 block sums (196 blocks x 256)
#define SCAN_B 256
#define SCAN_NB ((N_NODES + SCAN_B - 1) / SCAN_B)   // 196

__global__ __launch_bounds__(SCAN_B)
void scan_p1(const int* __restrict__ deg, int* __restrict__ bsum) {
    __shared__ int sh[SCAN_B];
    int i = blockIdx.x * SCAN_B + threadIdx.x;
    sh[threadIdx.x] = (i < N_NODES) ? deg[i] : 0;
    __syncthreads();
    for (int d = SCAN_B / 2; d > 0; d >>= 1) {
        if (threadIdx.x < d) sh[threadIdx.x] += sh[threadIdx.x + d];
        __syncthreads();
    }
    if (threadIdx.x == 0) bsum[blockIdx.x] = sh[0];
}

// phase 2: single block exclusive-scans the 196 block sums
__global__ __launch_bounds__(256)
void scan_p2(const int* __restrict__ bsum, int* __restrict__ boff) {
    __shared__ int sh[256];
    int t = threadIdx.x;
    sh[t] = (t < SCAN_NB) ? bsum[t] : 0;
    __syncthreads();
    for (int d = 1; d < 256; d <<= 1) {
        int v = (t >= d) ? sh[t - d] : 0;
        __syncthreads();
        sh[t] += v;
        __syncthreads();
    }
    if (t < SCAN_NB) boff[t] = (t == 0) ? 0 : sh[t - 1];
}

// phase 3: per-block exclusive scan + base offset -> off/cursor
__global__ __launch_bounds__(SCAN_B)
void scan_p3(const int* __restrict__ deg, const int* __restrict__ boff,
             int* __restrict__ off, int* __restrict__ cursor) {
    __shared__ int sh[SCAN_B];
    int i = blockIdx.x * SCAN_B + threadIdx.x;
    int t = threadIdx.x;
    int v = (i < N_NODES) ? deg[i] : 0;
    sh[t] = v;
    __syncthreads();
    for (int d = 1; d < SCAN_B; d <<= 1) {
        int u = (t >= d) ? sh[t - d] : 0;
        __syncthreads();
        sh[t] += u;
        __syncthreads();
    }
    int base = boff[blockIdx.x];
    if (i < N_NODES) {
        int incl = base + sh[t];
        off[i + 1] = incl;
        cursor[i]  = incl - v;
        if (i == 0) off[0] = 0;
    }
}

__global__ void fill_kernel(const void* __restrict__ raw, int* __restrict__ cursor,
                            int* __restrict__ esrc, int E) {
    int e = blockIdx.x * blockDim.x + threadIdx.x;
    if (e >= E) return;
    int src = edge_at(raw, e);
    int dst = edge_at(raw, (long long)E + e);
    int pos = atomicAdd(&cursor[dst], 1);
    esrc[pos] = src;
}

// ---------------------------------------------------------------------------
// All-weights tf32 quantization in one launch (elementwise, same layout)
// ---------------------------------------------------------------------------
__global__ void quantw_all(const float* __restrict__ w10, const float* __restrict__ w20,
                           const float* __restrict__ w11, const float* __restrict__ w21,
                           const float* __restrict__ wo,  float* __restrict__ dst) {
    int i = blockIdx.x * blockDim.x + threadIdx.x;
    if (i >= 262144) return;
    float v;
    if      (i < 32768)  v = w10[i];
    else if (i < 98304)  v = w20[i - 32768];
    else if (i < 163840) v = w11[i - 98304];
    else if (i < 229376) v = w21[i - 163840];
    else                 v = wo [i - 229376];
    dst[i] = qtf(v);
}

// ---------------------------------------------------------------------------
// Fused gather + GIN combine (tf32-rounded output)
// ---------------------------------------------------------------------------
__device__ __forceinline__ void f4add(float4& a, const float4& b) {
    a.x += b.x; a.y += b.y; a.z += b.z; a.w += b.w;
}
__device__ __forceinline__ float4 q4(float4 v) {
    return make_float4(qtf(v.x), qtf(v.y), qtf(v.z), qtf(v.w));
}

template<int D4>
__global__ __launch_bounds__(256)
void gather_combine(const float4* __restrict__ x,
                    const int* __restrict__ off,
                    const int* __restrict__ esrc,
                    const float* __restrict__ epsp,
                    float4* __restrict__ out) {
    int node = blockIdx.x * 8 + (threadIdx.x >> 5);
    if (node >= N_NODES) return;
    int lane = threadIdx.x & 31;
    float scale = 1.f + __ldg(epsp);
    int s = off[node], e = off[node + 1];

    float4 a0 = make_float4(0.f, 0.f, 0.f, 0.f);
    float4 a1 = make_float4(0.f, 0.f, 0.f, 0.f);

    int i = s;
    for (; i + 1 < e; i += 2) {
        const float4* r0 = x + (size_t)esrc[i]     * D4;
        const float4* r1 = x + (size_t)esrc[i + 1] * D4;
        f4add(a0, __ldg(r0 + lane));
        f4add(a0, __ldg(r1 + lane));
        if (D4 == 64) {
            f4add(a1, __ldg(r0 + lane + 32));
            f4add(a1, __ldg(r1 + lane + 32));
        }
    }
    if (i < e) {
        const float4* r0 = x + (size_t)esrc[i] * D4;
        f4add(a0, __ldg(r0 + lane));
        if (D4 == 64) f4add(a1, __ldg(r0 + lane + 32));
    }
    {
        const float4* sp = x + (size_t)node * D4;
        float4 v = __ldg(sp + lane);
        a0.x = fmaf(scale, v.x, a0.x);
        a0.y = fmaf(scale, v.y, a0.y);
        a0.z = fmaf(scale, v.z, a0.z);
        a0.w = fmaf(scale, v.w, a0.w);
        if (D4 == 64) {
            float4 w = __ldg(sp + lane + 32);
            a1.x = fmaf(scale, w.x, a1.x);
            a1.y = fmaf(scale, w.y, a1.y);
            a1.z = fmaf(scale, w.z, a1.z);
            a1.w = fmaf(scale, w.w, a1.w);
        }
    }
    out[(size_t)node * D4 + lane] = q4(a0);
    if (D4 == 64) out[(size_t)node * D4 + lane + 32] = q4(a1);
}

// ---------------------------------------------------------------------------
// TF32 mma.sync GEMM, 3-stage cp.async pipeline (1 barrier / K-chunk).
//   C = op(A @ W + bias);  BM=128, BN=128, BK=32; 256 thr, 8 warps (4m x 2n).
//   A smem [m][k] stride 36; B smem [k][n] stride 136 (both conflict-free).
//   Inputs must already be tf32-rounded f32.
// ---------------------------------------------------------------------------
#define SA 36
#define SB 136
#define ASTAGE (128 * SA)          // words per A stage
#define BSTAGE (32  * SB)          // words per B stage
#define STG    (ASTAGE + BSTAGE)
#define GEMM_SMEM_BYTES (3 * STG * 4)

template<bool RELU, bool QUANT>
__global__ __launch_bounds__(256, 2)
void gemm_cp(const float* __restrict__ A,
             const float* __restrict__ W,
             const float* __restrict__ bias,
             float* __restrict__ C,
             int M, int K, int Ncol) {
    extern __shared__ float dsm[];
    const uint32_t sbase = smem_u32(dsm);

    const int tid  = threadIdx.x;
    const int lane = tid & 31;
    const int warp = tid >> 5;
    const int wm   = warp >> 1;        // 0..3
    const int wn   = warp & 1;         // 0..1
    const int gid  = lane >> 2;        // 0..7
    const int tig  = lane & 3;         // 0..3

    const int row0 = blockIdx.x * 128;
    const int col0 = blockIdx.y * 128;

    float acc[2][8][4];
    #pragma unroll
    for (int mt = 0; mt < 2; mt++)
        #pragma unroll
        for (int nt = 0; nt < 8; nt++)
            #pragma unroll
            for (int i = 0; i < 4; i++)
                acc[mt][nt][i] = 0.f;

    auto issue = [&](int c) {
        const int k0  = c * 32;
        const int stg = c % 3;
        const uint32_t abase = sbase + (stg * STG) * 4;
        #pragma unroll
        for (int i = 0; i < 4; i++) {
            int chunk = tid + 256 * i;          // 0..1023
            int row = chunk >> 3, c16 = chunk & 7;
            bool ok = (row0 + row) < M;
            const float* src = ok ? (A + (size_t)(row0 + row) * K + k0 + c16 * 4) : A;
            cpa16(abase + (row * SA + c16 * 4) * 4, src, ok ? 16 : 0);
        }
        const uint32_t bbase = abase + ASTAGE * 4;
        #pragma unroll
        for (int i = 0; i < 4; i++) {
            int chunk = tid + 256 * i;          // 0..1023
            int kr = chunk >> 5, n16 = chunk & 31;
            const float* src = W + (size_t)(k0 + kr) * Ncol + col0 + n16 * 4;
            cpa16(bbase + (kr * SB + n16 * 4) * 4, src, 16);
        }
    };

    auto compute = [&](int c) {
        const int stg = c % 3;
        const float* As = dsm + stg * STG;
        const float* Bs = As + ASTAGE;
        #pragma unroll
        for (int ks = 0; ks < 4; ks++) {
            const int kk = ks * 8;
            uint32_t af[2][4];
            #pragma unroll
            for (int mt = 0; mt < 2; mt++) {
                int r = wm * 32 + mt * 16 + gid;
                af[mt][0] = __float_as_uint(As[ r      * SA + kk + tig    ]);
                af[mt][1] = __float_as_uint(As[(r + 8) * SA + kk + tig    ]);
                af[mt][2] = __float_as_uint(As[ r      * SA + kk + tig + 4]);
                af[mt][3] = __float_as_uint(As[(r + 8) * SA + kk + tig + 4]);
            }
            uint32_t bf[8][2];
            #pragma unroll
            for (int nt = 0; nt < 8; nt++) {
                int n = wn * 64 + nt * 8 + gid;
                bf[nt][0] = __float_as_uint(Bs[(kk + tig)     * SB + n]);
                bf[nt][1] = __float_as_uint(Bs[(kk + tig + 4) * SB + n]);
            }
            #pragma unroll
            for (int mt = 0; mt < 2; mt++)
                #pragma unroll
                for (int nt = 0; nt < 8; nt++)
                    mma8(acc[mt][nt], af[mt], bf[nt]);
        }
    };

    const int NC = K / 32;
    issue(0); cp_commit();
    issue(1); cp_commit();

    for (int c = 0; c < NC; c++) {
        cp_wait<1>();
        __syncthreads();
        if (c + 2 < NC) issue(c + 2);
        cp_commit();
        compute(c);
    }

    // ---- epilogue ----
    #pragma unroll
    for (int mt = 0; mt < 2; mt++) {
        #pragma unroll
        for (int nt = 0; nt < 8; nt++) {
            int col = col0 + wn * 64 + nt * 8 + 2 * tig;
            float b0 = __ldg(bias + col);
            float b1 = __ldg(bias + col + 1);
            int r = row0 + wm * 32 + mt * 16 + gid;
            float v0 = acc[mt][nt][0] + b0;
            float v1 = acc[mt][nt][1] + b1;
            float v2 = acc[mt][nt][2] + b0;
            float v3 = acc[mt][nt][3] + b1;
            if (RELU) {
                v0 = fmaxf(v0, 0.f); v1 = fmaxf(v1, 0.f);
                v2 = fmaxf(v2, 0.f); v3 = fmaxf(v3, 0.f);
            }
            if (QUANT) {
                v0 = qtf(v0); v1 = qtf(v1); v2 = qtf(v2); v3 = qtf(v3);
            }
            if (r < M)
                *reinterpret_cast<float2*>(C + (size_t)r * Ncol + col) = make_float2(v0, v1);
            if (r + 8 < M)
                *reinterpret_cast<float2*>(C + (size_t)(r + 8) * Ncol + col) = make_float2(v2, v3);
        }
    }
}

// ---------------------------------------------------------------------------
// Launch
// ---------------------------------------------------------------------------
extern "C" void kernel_launch(void* const* d_in, const int* in_sizes, int n_in,
                              void* d_out, int out_size) {
    const float* x    = (const float*)d_in[0];
    const void*  eiRaw= d_in[1];
    const float* eps0 = (const float*)d_in[2];
    const float* W1_0 = (const float*)d_in[3];
    const float* b1_0 = (const float*)d_in[4];
    const float* W2_0 = (const float*)d_in[5];
    const float* b2_0 = (const float*)d_in[6];
    const float* eps1 = (const float*)d_in[7];
    const float* W1_1 = (const float*)d_in[8];
    const float* b1_1 = (const float*)d_in[9];
    const float* W2_1 = (const float*)d_in[10];
    const float* b2_1 = (const float*)d_in[11];
    const float* Wo   = (const float*)d_in[12];
    const float* bo   = (const float*)d_in[13];
    float*       out  = (float*)d_out;

    const int two_e = in_sizes[1];
    const int E     = two_e / 2;

    float *comb, *t1, *h0, *wq;
    int *deg, *cur, *off, *esrc, *bsum, *boff;
    cudaGetSymbolAddress((void**)&comb, g_comb);
    cudaGetSymbolAddress((void**)&t1,   g_t1);
    cudaGetSymbolAddress((void**)&h0,   g_h0);
    cudaGetSymbolAddress((void**)&wq,   g_wq);
    cudaGetSymbolAddress((void**)&deg,  g_deg);
    cudaGetSymbolAddress((void**)&cur,  g_cur);
    cudaGetSymbolAddress((void**)&off,  g_off);
    cudaGetSymbolAddress((void**)&esrc, g_esrc);
    cudaGetSymbolAddress((void**)&bsum, g_bsum);
    cudaGetSymbolAddress((void**)&boff, g_boff);

    float* W1_0q = wq;                   // 32768
    float* W2_0q = wq + 32768;           // 65536
    float* W1_1q = wq + 98304;           // 65536
    float* W2_1q = wq + 163840;          // 65536
    float* Woq   = wq + 229376;          // 32768

    cudaFuncSetAttribute(gemm_cp<true,  true >,
                         cudaFuncAttributeMaxDynamicSharedMemorySize, GEMM_SMEM_BYTES);
    cudaFuncSetAttribute(gemm_cp<false, false>,
                         cudaFuncAttributeMaxDynamicSharedMemorySize, GEMM_SMEM_BYTES);
    cudaFuncSetAttribute(gemm_cp<false, true >,
                         cudaFuncAttributeMaxDynamicSharedMemorySize, GEMM_SMEM_BYTES);

    // ---- detect edge dtype ----
    int nscan = two_e < 128 ? two_e : 128;
    detect_kernel<<<1, 32>>>(eiRaw, nscan);

    // ---- CSR build (from raw edges) ----
    zero_int_kernel<<<(N_NODES + 255) / 256, 256>>>(deg, N_NODES);
    hist_kernel<<<(E + 255) / 256, 256>>>(eiRaw, deg, E);
    scan_p1<<<SCAN_NB, SCAN_B>>>(deg, bsum);
    scan_p2<<<1, 256>>>(bsum, boff);
    scan_p3<<<SCAN_NB, SCAN_B>>>(deg, boff, off, cur);
    fill_kernel<<<(E + 255) / 256, 256>>>(eiRaw, cur, esrc, E);

    // ---- quantize all weights in one launch ----
    quantw_all<<<1024, 256>>>(W1_0, W2_0, W1_1, W2_1, Wo, wq);

    dim3 gH((N_NODES + 127) / 128, 2);   // Ncol=256
    dim3 gO((N_NODES + 127) / 128, 1);   // Ncol=128
    int  gGather = (N_NODES + 7) / 8;

    // ---- layer 0 ----
    gather_combine<32><<<gGather, 256>>>((const float4*)x, off, esrc, eps0, (float4*)comb);
    gemm_cp<true,  true ><<<gH, 256, GEMM_SMEM_BYTES>>>(comb, W1_0q, b1_0, t1, N_NODES, D_IN,  D_HID);
    gemm_cp<false, false><<<gH, 256, GEMM_SMEM_BYTES>>>(t1,   W2_0q, b2_0, h0, N_NODES, D_HID, D_HID);

    // ---- layer 1 ----
    gather_combine<64><<<gGather, 256>>>((const float4*)h0, off, esrc, eps1, (float4*)comb);
    gemm_cp<true,  true ><<<gH, 256, GEMM_SMEM_BYTES>>>(comb, W1_1q, b1_1, t1, N_NODES, D_HID, D_HID);
    gemm_cp<false, true ><<<gH, 256, GEMM_SMEM_BYTES>>>(t1,   W2_1q, b2_1, h0, N_NODES, D_HID, D_HID); // h1

    // ---- fc_out ----
    gemm_cp<false, false><<<gO, 256, GEMM_SMEM_BYTES>>>(h0, Woq, bo, out, N_NODES, D_HID, D_IN);
}